// round 14
// baseline (speedup 1.0000x reference)
#include <cuda_runtime.h>
#include <math.h>

#define BI 256
#define BC 256
#define LR 36
#define TT 64
#define DD 1024
#define DR 256
#define EPS 1e-8f

// ---------------- scratch: one contiguous zeroed buffer ----------------
#define ZB_CAPSUM 0
#define ZB_CC     (BC * DD)
#define ZB_DOT    (BC * DD + BI * 3 * DD)
#define ZB_TOTAL  (BC * DD + BI * 3 * DD + BI * 3 * BC)
__device__ float g_zbuf[ZB_TOTAL];
#define g_capsum (g_zbuf + ZB_CAPSUM)
#define g_cc     (g_zbuf + ZB_CC)
#define g_dot    (g_zbuf + ZB_DOT)

__device__ float g_pr[3 * DD];
__device__ float g_pb2[3];
__device__ float g_cb2;
__device__ float g_capv[BC * DD];
__device__ float g_w[BC * 3];
__device__ float g_bb[BC];
__device__ float g_cmat[BI * 3 * DD];
__device__ float g_G[BI * 6];
__device__ float g_h[BI * 3];

// ---------------- tf32 helpers ----------------
__device__ __forceinline__ void tf32_split(float x, unsigned& hi, unsigned& lo) {
    asm("cvt.rna.tf32.f32 %0, %1;" : "=r"(hi) : "f"(x));
    float r = x - __uint_as_float(hi);
    asm("cvt.rna.tf32.f32 %0, %1;" : "=r"(lo) : "f"(r));
}
__device__ __forceinline__ void mma_tf32(float* c, const unsigned* a, const unsigned* b) {
    asm("mma.sync.aligned.m16n8k8.row.col.f32.tf32.tf32.f32 "
        "{%0,%1,%2,%3}, {%4,%5,%6,%7}, {%8,%9}, {%0,%1,%2,%3};"
        : "+f"(c[0]), "+f"(c[1]), "+f"(c[2]), "+f"(c[3])
        : "r"(a[0]), "r"(a[1]), "r"(a[2]), "r"(a[3]), "r"(b[0]), "r"(b[1]));
}

// ---------------- K0: tiny precompute ----------------
__global__ void k0_prep(const float* __restrict__ red_w, const float* __restrict__ red_b,
                        const float* __restrict__ proj_w, const float* __restrict__ proj_b,
                        const float* __restrict__ conv_b) {
    if (blockIdx.x < 8) {
        int d = blockIdx.x * 128 + threadIdx.x;
        float a0 = 0.f, a1 = 0.f, a2 = 0.f;
        for (int e = 0; e < DR; e++) {
            float rw = red_w[e * DD + d];
            a0 += proj_w[e] * rw;
            a1 += proj_w[DR + e] * rw;
            a2 += proj_w[2 * DR + e] * rw;
        }
        g_pr[d] = a0; g_pr[DD + d] = a1; g_pr[2 * DD + d] = a2;
    } else {
        __shared__ float s[128];
        int tid = threadIdx.x;
        for (int k = 0; k < 3; k++) {
            float p = 0.f;
            for (int e = tid; e < DR; e += 128) p += proj_w[k * DR + e] * red_b[e];
            s[tid] = p; __syncthreads();
            for (int off = 64; off > 0; off >>= 1) { if (tid < off) s[tid] += s[tid + off]; __syncthreads(); }
            if (tid == 0) g_pb2[k] = s[0] + proj_b[k];
            __syncthreads();
        }
        float c = 0.f;
        for (int d = tid; d < DD; d += 128) { float v = conv_b[d]; c += v * v; }
        s[tid] = c; __syncthreads();
        for (int off = 64; off > 0; off >>= 1) { if (tid < off) s[tid] += s[tid + off]; __syncthreads(); }
        if (tid == 0) g_cb2 = s[0];
    }
}

// ---------------- K1a: t-split caption sums ----------------
__global__ void k1a_capsum(const float* __restrict__ cap, const int* __restrict__ lens) {
    int b = blockIdx.x;
    int z = blockIdx.y;
    int tid = threadIdx.x;
    int len = lens[b];
    int t0 = z * 16;
    if (t0 >= len) return;
    int t1 = min(len, t0 + 16);
    const float* base = cap + (size_t)b * TT * DD;
    float acc[4] = {0.f, 0.f, 0.f, 0.f};
    for (int t = t0; t < t1; t++) {
        const float* row = base + t * DD;
        #pragma unroll
        for (int j = 0; j < 4; j++) acc[j] += row[tid + 256 * j];
    }
    #pragma unroll
    for (int j = 0; j < 4; j++) atomicAdd(&g_capsum[b * DD + tid + 256 * j], acc[j]);
}

// ---------------- K1b: normalize + softmax weights ----------------
__global__ void k1b_caption(const int* __restrict__ lens, const float* __restrict__ conv_b) {
    int b = blockIdx.x;
    int tid = threadIdx.x;
    int len = lens[b];
    float invlen = 1.0f / (float)len;
    float acc[4];
    #pragma unroll
    for (int j = 0; j < 4; j++) acc[j] = g_capsum[b * DD + tid + 256 * j] * invlen;

    __shared__ float s[256];
    __shared__ float res[6];
    float vals[5];
    vals[0] = acc[0] * acc[0] + acc[1] * acc[1] + acc[2] * acc[2] + acc[3] * acc[3];
    #pragma unroll
    for (int k = 0; k < 3; k++) {
        float v = 0.f;
        #pragma unroll
        for (int j = 0; j < 4; j++) v += g_pr[k * DD + tid + 256 * j] * acc[j];
        vals[1 + k] = v;
    }
    {
        float v = 0.f;
        #pragma unroll
        for (int j = 0; j < 4; j++) v += conv_b[tid + 256 * j] * acc[j];
        vals[4] = v;
    }
    for (int r = 0; r < 5; r++) {
        s[tid] = vals[r]; __syncthreads();
        for (int off = 128; off > 0; off >>= 1) { if (tid < off) s[tid] += s[tid + off]; __syncthreads(); }
        if (tid == 0) res[r] = s[0];
        __syncthreads();
    }
    if (tid == 0) {
        float inv = 1.0f / (sqrtf(res[0]) + EPS);
        float l0 = res[1] + g_pb2[0], l1 = res[2] + g_pb2[1], l2 = res[3] + g_pb2[2];
        float m = fmaxf(l0, fmaxf(l1, l2));
        float e0 = expf(l0 - m), e1 = expf(l1 - m), e2 = expf(l2 - m);
        float si = 1.0f / (e0 + e1 + e2);
        g_w[b * 3 + 0] = e0 * si;
        g_w[b * 3 + 1] = e1 * si;
        g_w[b * 3 + 2] = e2 * si;
        g_bb[b] = res[4] * inv;
        res[5] = inv;
    }
    __syncthreads();
    float inv = res[5];
    #pragma unroll
    for (int j = 0; j < 4; j++) g_capv[b * DD + tid + 256 * j] = acc[j] * inv;
}

// ---------------- K2: image shifted region sums ----------------
__global__ void k2_image(const float* __restrict__ img) {
    int i = blockIdx.x;
    int tid = threadIdx.x;
    const float* base = img + (size_t)i * LR * DD;
    float acc[4] = {0.f, 0.f, 0.f, 0.f}, r0[4], rL[4];
    #pragma unroll
    for (int j = 0; j < 4; j++) r0[j] = base[tid + 256 * j];
    for (int t = 0; t < LR; t++) {
        #pragma unroll
        for (int j = 0; j < 4; j++) acc[j] += base[t * DD + tid + 256 * j];
    }
    #pragma unroll
    for (int j = 0; j < 4; j++) rL[j] = base[(LR - 1) * DD + tid + 256 * j];
    const float invL = 1.0f / (float)LR;
    #pragma unroll
    for (int j = 0; j < 4; j++) {
        int d = tid + 256 * j;
        g_cmat[(size_t)(i * 3 + 0) * DD + d] = (acc[j] - rL[j]) * invL;
        g_cmat[(size_t)(i * 3 + 1) * DD + d] = acc[j] * invL;
        g_cmat[(size_t)(i * 3 + 2) * DD + d] = (acc[j] - r0[j]) * invL;
    }
}

// ---------------- zero kernel ----------------
__global__ void kzero(float* __restrict__ p, int n4) {
    int i = blockIdx.x * 256 + threadIdx.x;
    if (i < n4) reinterpret_cast<float4*>(p)[i] = make_float4(0.f, 0.f, 0.f, 0.f);
}

// ---------------- GEMM NT split-K, 3xTF32, INTERLEAVED pre-split smem ---------------
// BM=64, BN=64, BK=16, 128 threads = 4 warps (2x2 warp grid, 32x32 per warp).
// Each smem element stores (hi, lo) adjacent as uint2 -> one LDS.64 per fragment pair;
// inner loop is pure LDS.64 + HMMA (no cvt).
template <int M, int N, int KA, int KLEN>
__device__ __forceinline__ void gemm_nt_tf32(const float* __restrict__ A,
                                             const float* __restrict__ B,
                                             float* __restrict__ C) {
    __shared__ uint2 As2[64][20];   // [row][k] = (hi, lo); row stride 160B: conflict-free
    __shared__ uint2 Bs2[64][20];
    int t = threadIdx.x;
    int lane = t & 31;
    int warp = t >> 5;
    int wm = (warp & 1) * 32;
    int wn = (warp >> 1) * 32;
    int bm = blockIdx.y * 64;
    int bn = blockIdx.x * 64;

    const float* Ab = A + blockIdx.z * KLEN;
    const float* Bb = B + blockIdx.z * KLEN;

    int r0 = t >> 2;            int kk0 = (t & 3) * 4;
    int r1 = (t + 128) >> 2;    int kk1 = ((t + 128) & 3) * 4;

    float acc[2][4][4];
    #pragma unroll
    for (int i = 0; i < 2; i++)
        #pragma unroll
        for (int j = 0; j < 4; j++)
            #pragma unroll
            for (int r = 0; r < 4; r++) acc[i][j][r] = 0.f;

    int qr = lane >> 2;   // 0..7
    int qc = lane & 3;    // 0..3

    float4 va0 = *reinterpret_cast<const float4*>(&Ab[(size_t)(bm + r0) * KA + kk0]);
    float4 va1 = *reinterpret_cast<const float4*>(&Ab[(size_t)(bm + r1) * KA + kk1]);
    float4 vb0 = *reinterpret_cast<const float4*>(&Bb[(size_t)(bn + r0) * KA + kk0]);
    float4 vb1 = *reinterpret_cast<const float4*>(&Bb[(size_t)(bn + r1) * KA + kk1]);

    for (int k0 = 0; k0 < KLEN; k0 += 16) {
        // split at store time (once per CTA element); interleaved (hi,lo) uint2 pairs
        {
            uint4 u;
            tf32_split(va0.x, u.x, u.y); tf32_split(va0.y, u.z, u.w);
            *reinterpret_cast<uint4*>(&As2[r0][kk0]) = u;
            tf32_split(va0.z, u.x, u.y); tf32_split(va0.w, u.z, u.w);
            *reinterpret_cast<uint4*>(&As2[r0][kk0 + 2]) = u;
            tf32_split(va1.x, u.x, u.y); tf32_split(va1.y, u.z, u.w);
            *reinterpret_cast<uint4*>(&As2[r1][kk1]) = u;
            tf32_split(va1.z, u.x, u.y); tf32_split(va1.w, u.z, u.w);
            *reinterpret_cast<uint4*>(&As2[r1][kk1 + 2]) = u;
            tf32_split(vb0.x, u.x, u.y); tf32_split(vb0.y, u.z, u.w);
            *reinterpret_cast<uint4*>(&Bs2[r0][kk0]) = u;
            tf32_split(vb0.z, u.x, u.y); tf32_split(vb0.w, u.z, u.w);
            *reinterpret_cast<uint4*>(&Bs2[r0][kk0 + 2]) = u;
            tf32_split(vb1.x, u.x, u.y); tf32_split(vb1.y, u.z, u.w);
            *reinterpret_cast<uint4*>(&Bs2[r1][kk1]) = u;
            tf32_split(vb1.z, u.x, u.y); tf32_split(vb1.w, u.z, u.w);
            *reinterpret_cast<uint4*>(&Bs2[r1][kk1 + 2]) = u;
        }
        __syncthreads();

        if (k0 + 16 < KLEN) {
            va0 = *reinterpret_cast<const float4*>(&Ab[(size_t)(bm + r0) * KA + k0 + 16 + kk0]);
            va1 = *reinterpret_cast<const float4*>(&Ab[(size_t)(bm + r1) * KA + k0 + 16 + kk1]);
            vb0 = *reinterpret_cast<const float4*>(&Bb[(size_t)(bn + r0) * KA + k0 + 16 + kk0]);
            vb1 = *reinterpret_cast<const float4*>(&Bb[(size_t)(bn + r1) * KA + k0 + 16 + kk1]);
        }

        #pragma unroll
        for (int k8 = 0; k8 < 16; k8 += 8) {
            unsigned ahi[2][4], alo[2][4];
            #pragma unroll
            for (int i = 0; i < 2; i++) {
                int rb = wm + i * 16;
                uint2 p0 = As2[rb + qr][k8 + qc];
                uint2 p1 = As2[rb + 8 + qr][k8 + qc];
                uint2 p2 = As2[rb + qr][k8 + 4 + qc];
                uint2 p3 = As2[rb + 8 + qr][k8 + 4 + qc];
                ahi[i][0] = p0.x; alo[i][0] = p0.y;
                ahi[i][1] = p1.x; alo[i][1] = p1.y;
                ahi[i][2] = p2.x; alo[i][2] = p2.y;
                ahi[i][3] = p3.x; alo[i][3] = p3.y;
            }
            unsigned bhi[4][2], blo[4][2];
            #pragma unroll
            for (int j = 0; j < 4; j++) {
                int nb = wn + j * 8;
                uint2 q0 = Bs2[nb + qr][k8 + qc];
                uint2 q1 = Bs2[nb + qr][k8 + 4 + qc];
                bhi[j][0] = q0.x; blo[j][0] = q0.y;
                bhi[j][1] = q1.x; blo[j][1] = q1.y;
            }
            #pragma unroll
            for (int i = 0; i < 2; i++)
                #pragma unroll
                for (int j = 0; j < 4; j++) {
                    mma_tf32(acc[i][j], ahi[i], bhi[j]);
                    mma_tf32(acc[i][j], ahi[i], blo[j]);
                    mma_tf32(acc[i][j], alo[i], bhi[j]);
                }
        }
        __syncthreads();
    }

    #pragma unroll
    for (int i = 0; i < 2; i++)
        #pragma unroll
        for (int j = 0; j < 4; j++) {
            int row = bm + wm + i * 16 + qr;
            int col = bn + wn + j * 8 + qc * 2;
            atomicAdd(&C[(size_t)row * N + col],       acc[i][j][0]);
            atomicAdd(&C[(size_t)row * N + col + 1],   acc[i][j][1]);
            atomicAdd(&C[(size_t)(row + 8) * N + col],     acc[i][j][2]);
            atomicAdd(&C[(size_t)(row + 8) * N + col + 1], acc[i][j][3]);
        }
}

__global__ void k3_gemm_cc(const float* __restrict__ conv_w) {
    gemm_nt_tf32<BI * 3, DD, DD, 256>(g_cmat, conv_w, g_cc);
}
__global__ void k5_gemm_dot() {
    gemm_nt_tf32<BI * 3, BC, DD, 128>(g_cc, g_capv, g_dot);
}

// ---------------- K4: per-image Gram + bias dots (float4, 256 thr, shuffle) --------
__global__ void k4_gram(const float* __restrict__ conv_b) {
    int i = blockIdx.x;
    int tid = threadIdx.x;
    const float4* c0 = reinterpret_cast<const float4*>(g_cc + (size_t)(i * 3 + 0) * DD);
    const float4* c1 = reinterpret_cast<const float4*>(g_cc + (size_t)(i * 3 + 1) * DD);
    const float4* c2 = reinterpret_cast<const float4*>(g_cc + (size_t)(i * 3 + 2) * DD);
    const float4* cb = reinterpret_cast<const float4*>(conv_b);
    float4 x0 = c0[tid], x1 = c1[tid], x2 = c2[tid], b4 = cb[tid];
    float a[9];
    a[0] = x0.x*x0.x + x0.y*x0.y + x0.z*x0.z + x0.w*x0.w;
    a[1] = x0.x*x1.x + x0.y*x1.y + x0.z*x1.z + x0.w*x1.w;
    a[2] = x0.x*x2.x + x0.y*x2.y + x0.z*x2.z + x0.w*x2.w;
    a[3] = x1.x*x1.x + x1.y*x1.y + x1.z*x1.z + x1.w*x1.w;
    a[4] = x1.x*x2.x + x1.y*x2.y + x1.z*x2.z + x1.w*x2.w;
    a[5] = x2.x*x2.x + x2.y*x2.y + x2.z*x2.z + x2.w*x2.w;
    a[6] = x0.x*b4.x + x0.y*b4.y + x0.z*b4.z + x0.w*b4.w;
    a[7] = x1.x*b4.x + x1.y*b4.y + x1.z*b4.z + x1.w*b4.w;
    a[8] = x2.x*b4.x + x2.y*b4.y + x2.z*b4.z + x2.w*b4.w;

    __shared__ float sred[8][9];
    int lane = tid & 31, wid = tid >> 5;
    #pragma unroll
    for (int r = 0; r < 9; r++) {
        float v = a[r];
        #pragma unroll
        for (int off = 16; off > 0; off >>= 1) v += __shfl_down_sync(0xffffffffu, v, off);
        if (lane == 0) sred[wid][r] = v;
    }
    __syncthreads();
    if (wid == 0) {
        #pragma unroll
        for (int r = 0; r < 9; r++) {
            float v = (lane < 8) ? sred[lane][r] : 0.f;
            #pragma unroll
            for (int off = 4; off > 0; off >>= 1) v += __shfl_down_sync(0xffffffffu, v, off);
            if (lane == 0) { if (r < 6) g_G[i * 6 + r] = v; else g_h[i * 3 + (r - 6)] = v; }
        }
    }
}

// ---------------- K6: final similarity ----------------
__global__ void k6_final(float* __restrict__ out) {
    int i = blockIdx.x;
    int b = threadIdx.x;
    float w0 = g_w[b * 3 + 0], w1 = g_w[b * 3 + 1], w2 = g_w[b * 3 + 2];
    const float* dp = g_dot + (size_t)(i * 3) * BC + b;
    float num = w0 * dp[0] + w1 * dp[BC] + w2 * dp[2 * BC] + g_bb[b];
    const float* G = g_G + i * 6;
    const float* h = g_h + i * 3;
    float n2 = w0 * w0 * G[0] + 2.f * w0 * w1 * G[1] + 2.f * w0 * w2 * G[2]
             + w1 * w1 * G[3] + 2.f * w1 * w2 * G[4] + w2 * w2 * G[5]
             + 2.f * (w0 * h[0] + w1 * h[1] + w2 * h[2]) + g_cb2;
    out[i * BC + b] = num / (sqrtf(n2) + EPS);
}

// ---------------- launch (R11 fork-join schedule, verbatim) ----------------
extern "C" void kernel_launch(void* const* d_in, const int* in_sizes, int n_in,
                              void* d_out, int out_size) {
    const float* img    = (const float*)d_in[0];
    const float* cap    = (const float*)d_in[1];
    const int*   lens   = (const int*)d_in[2];
    const float* red_w  = (const float*)d_in[3];
    const float* red_b  = (const float*)d_in[4];
    const float* proj_w = (const float*)d_in[5];
    const float* proj_b = (const float*)d_in[6];
    const float* conv_w = (const float*)d_in[7];
    const float* conv_b = (const float*)d_in[8];
    float* out = (float*)d_out;

    float* zbuf = nullptr;
    cudaGetSymbolAddress((void**)&zbuf, g_zbuf);

    // Streams/events created per call; not destroyed (host handles only; see R7 note).
    cudaStream_t s2;
    cudaStreamCreateWithFlags(&s2, cudaStreamNonBlocking);
    cudaEvent_t e_zero, e_cap;
    cudaEventCreateWithFlags(&e_zero, cudaEventDisableTiming);
    cudaEventCreateWithFlags(&e_cap, cudaEventDisableTiming);

    // main stream: zero everything, then image chain
    kzero<<<(ZB_TOTAL / 4 + 255) / 256, 256>>>(zbuf, ZB_TOTAL / 4);
    cudaEventRecord(e_zero, 0);

    // forked stream: caption chain
    cudaStreamWaitEvent(s2, e_zero, 0);
    k0_prep<<<9, 128, 0, s2>>>(red_w, red_b, proj_w, proj_b, conv_b);
    k1a_capsum<<<dim3(BC, 4), 256, 0, s2>>>(cap, lens);
    k1b_caption<<<BC, 256, 0, s2>>>(lens, conv_b);
    cudaEventRecord(e_cap, s2);

    // main stream: image chain (overlaps with caption chain)
    k2_image<<<BI, 256>>>(img);
    k3_gemm_cc<<<dim3(DD / 64, (BI * 3) / 64, 4), 128>>>(conv_w);
    k4_gram<<<BI, 256>>>(conv_b);

    // join, then final GEMM + similarity
    cudaStreamWaitEvent(0, e_cap, 0);
    k5_gemm_dot<<<dim3(BC / 64, (BI * 3) / 64, 8), 128>>>();
    k6_final<<<BI, 256>>>(out);
}

// round 15
// speedup vs baseline: 1.2880x; 1.2880x over previous
#include <cuda_runtime.h>
#include <math.h>

#define BI 256
#define BC 256
#define LR 36
#define TT 64
#define DD 1024
#define DR 256
#define EPS 1e-8f

// ---------------- scratch: one contiguous zeroed buffer ----------------
#define ZB_CAPSUM 0
#define ZB_CC     (BC * DD)
#define ZB_DOT    (BC * DD + BI * 3 * DD)
#define ZB_TOTAL  (BC * DD + BI * 3 * DD + BI * 3 * BC)
__device__ float g_zbuf[ZB_TOTAL];
#define g_capsum (g_zbuf + ZB_CAPSUM)
#define g_cc     (g_zbuf + ZB_CC)
#define g_dot    (g_zbuf + ZB_DOT)

__device__ float g_pr[3 * DD];
__device__ float g_pb2[3];
__device__ float g_cb2;
__device__ float g_capv[BC * DD];
__device__ float g_w[BC * 3];
__device__ float g_bb[BC];
__device__ float g_cmat[BI * 3 * DD];

// ---------------- tf32 helpers ----------------
__device__ __forceinline__ void tf32_split(float x, unsigned& hi, unsigned& lo) {
    asm("cvt.rna.tf32.f32 %0, %1;" : "=r"(hi) : "f"(x));
    float r = x - __uint_as_float(hi);
    asm("cvt.rna.tf32.f32 %0, %1;" : "=r"(lo) : "f"(r));
}
__device__ __forceinline__ void mma_tf32(float* c, const unsigned* a, const unsigned* b) {
    asm("mma.sync.aligned.m16n8k8.row.col.f32.tf32.tf32.f32 "
        "{%0,%1,%2,%3}, {%4,%5,%6,%7}, {%8,%9}, {%0,%1,%2,%3};"
        : "+f"(c[0]), "+f"(c[1]), "+f"(c[2]), "+f"(c[3])
        : "r"(a[0]), "r"(a[1]), "r"(a[2]), "r"(a[3]), "r"(b[0]), "r"(b[1]));
}

// ---------------- K0: tiny precompute ----------------
__global__ void k0_prep(const float* __restrict__ red_w, const float* __restrict__ red_b,
                        const float* __restrict__ proj_w, const float* __restrict__ proj_b,
                        const float* __restrict__ conv_b) {
    if (blockIdx.x < 8) {
        int d = blockIdx.x * 128 + threadIdx.x;
        float a0 = 0.f, a1 = 0.f, a2 = 0.f;
        for (int e = 0; e < DR; e++) {
            float rw = red_w[e * DD + d];
            a0 += proj_w[e] * rw;
            a1 += proj_w[DR + e] * rw;
            a2 += proj_w[2 * DR + e] * rw;
        }
        g_pr[d] = a0; g_pr[DD + d] = a1; g_pr[2 * DD + d] = a2;
    } else {
        __shared__ float s[128];
        int tid = threadIdx.x;
        for (int k = 0; k < 3; k++) {
            float p = 0.f;
            for (int e = tid; e < DR; e += 128) p += proj_w[k * DR + e] * red_b[e];
            s[tid] = p; __syncthreads();
            for (int off = 64; off > 0; off >>= 1) { if (tid < off) s[tid] += s[tid + off]; __syncthreads(); }
            if (tid == 0) g_pb2[k] = s[0] + proj_b[k];
            __syncthreads();
        }
        float c = 0.f;
        for (int d = tid; d < DD; d += 128) { float v = conv_b[d]; c += v * v; }
        s[tid] = c; __syncthreads();
        for (int off = 64; off > 0; off >>= 1) { if (tid < off) s[tid] += s[tid + off]; __syncthreads(); }
        if (tid == 0) g_cb2 = s[0];
    }
}

// ---------------- K1a: t-split caption sums ----------------
__global__ void k1a_capsum(const float* __restrict__ cap, const int* __restrict__ lens) {
    int b = blockIdx.x;
    int z = blockIdx.y;
    int tid = threadIdx.x;
    int len = lens[b];
    int t0 = z * 16;
    if (t0 >= len) return;
    int t1 = min(len, t0 + 16);
    const float* base = cap + (size_t)b * TT * DD;
    float acc[4] = {0.f, 0.f, 0.f, 0.f};
    for (int t = t0; t < t1; t++) {
        const float* row = base + t * DD;
        #pragma unroll
        for (int j = 0; j < 4; j++) acc[j] += row[tid + 256 * j];
    }
    #pragma unroll
    for (int j = 0; j < 4; j++) atomicAdd(&g_capsum[b * DD + tid + 256 * j], acc[j]);
}

// ---------------- K1b: normalize + softmax weights ----------------
__global__ void k1b_caption(const int* __restrict__ lens, const float* __restrict__ conv_b) {
    int b = blockIdx.x;
    int tid = threadIdx.x;
    int len = lens[b];
    float invlen = 1.0f / (float)len;
    float acc[4];
    #pragma unroll
    for (int j = 0; j < 4; j++) acc[j] = g_capsum[b * DD + tid + 256 * j] * invlen;

    __shared__ float s[256];
    __shared__ float res[6];
    float vals[5];
    vals[0] = acc[0] * acc[0] + acc[1] * acc[1] + acc[2] * acc[2] + acc[3] * acc[3];
    #pragma unroll
    for (int k = 0; k < 3; k++) {
        float v = 0.f;
        #pragma unroll
        for (int j = 0; j < 4; j++) v += g_pr[k * DD + tid + 256 * j] * acc[j];
        vals[1 + k] = v;
    }
    {
        float v = 0.f;
        #pragma unroll
        for (int j = 0; j < 4; j++) v += conv_b[tid + 256 * j] * acc[j];
        vals[4] = v;
    }
    for (int r = 0; r < 5; r++) {
        s[tid] = vals[r]; __syncthreads();
        for (int off = 128; off > 0; off >>= 1) { if (tid < off) s[tid] += s[tid + off]; __syncthreads(); }
        if (tid == 0) res[r] = s[0];
        __syncthreads();
    }
    if (tid == 0) {
        float inv = 1.0f / (sqrtf(res[0]) + EPS);
        float l0 = res[1] + g_pb2[0], l1 = res[2] + g_pb2[1], l2 = res[3] + g_pb2[2];
        float m = fmaxf(l0, fmaxf(l1, l2));
        float e0 = expf(l0 - m), e1 = expf(l1 - m), e2 = expf(l2 - m);
        float si = 1.0f / (e0 + e1 + e2);
        g_w[b * 3 + 0] = e0 * si;
        g_w[b * 3 + 1] = e1 * si;
        g_w[b * 3 + 2] = e2 * si;
        g_bb[b] = res[4] * inv;
        res[5] = inv;
    }
    __syncthreads();
    float inv = res[5];
    #pragma unroll
    for (int j = 0; j < 4; j++) g_capv[b * DD + tid + 256 * j] = acc[j] * inv;
}

// ---------------- K2: image shifted region sums (grid.y = 2 channel split) ----------
__global__ void k2_image(const float* __restrict__ img) {
    int i = blockIdx.x;
    int tid = threadIdx.x;
    int dbase = blockIdx.y * 512 + tid;   // this block covers channels [y*512, y*512+512)
    const float* base = img + (size_t)i * LR * DD;
    float acc[2] = {0.f, 0.f}, r0[2], rL[2];
    #pragma unroll
    for (int j = 0; j < 2; j++) r0[j] = base[dbase + 256 * j];
    for (int t = 0; t < LR; t++) {
        #pragma unroll
        for (int j = 0; j < 2; j++) acc[j] += base[t * DD + dbase + 256 * j];
    }
    #pragma unroll
    for (int j = 0; j < 2; j++) rL[j] = base[(LR - 1) * DD + dbase + 256 * j];
    const float invL = 1.0f / (float)LR;
    #pragma unroll
    for (int j = 0; j < 2; j++) {
        int d = dbase + 256 * j;
        g_cmat[(size_t)(i * 3 + 0) * DD + d] = (acc[j] - rL[j]) * invL;
        g_cmat[(size_t)(i * 3 + 1) * DD + d] = acc[j] * invL;
        g_cmat[(size_t)(i * 3 + 2) * DD + d] = (acc[j] - r0[j]) * invL;
    }
}

// ---------------- zero kernel ----------------
__global__ void kzero(float* __restrict__ p, int n4) {
    int i = blockIdx.x * 256 + threadIdx.x;
    if (i < n4) reinterpret_cast<float4*>(p)[i] = make_float4(0.f, 0.f, 0.f, 0.f);
}

// ---------------- GEMM NT split-K, 3xTF32 (R11 body, in-loop split) -----------------
// BM=64, BN=64, BK=16, 128 threads = 4 warps (2x2 warp grid, 32x32 per warp).
template <int M, int N, int KA, int KLEN>
__device__ __forceinline__ void gemm_nt_tf32(const float* __restrict__ A,
                                             const float* __restrict__ B,
                                             float* __restrict__ C) {
    __shared__ float As[64][20];   // [row][k], stride 20 -> conflict-free frag loads
    __shared__ float Bs[64][20];   // [n][k]
    int t = threadIdx.x;
    int lane = t & 31;
    int warp = t >> 5;
    int wm = (warp & 1) * 32;
    int wn = (warp >> 1) * 32;
    int bm = blockIdx.y * 64;
    int bn = blockIdx.x * 64;

    const float* Ab = A + blockIdx.z * KLEN;
    const float* Bb = B + blockIdx.z * KLEN;

    int r0 = t >> 2;            int kk0 = (t & 3) * 4;
    int r1 = (t + 128) >> 2;    int kk1 = ((t + 128) & 3) * 4;

    float acc[2][4][4];
    #pragma unroll
    for (int i = 0; i < 2; i++)
        #pragma unroll
        for (int j = 0; j < 4; j++)
            #pragma unroll
            for (int r = 0; r < 4; r++) acc[i][j][r] = 0.f;

    int qr = lane >> 2;   // 0..7
    int qc = lane & 3;    // 0..3

    float4 va0 = *reinterpret_cast<const float4*>(&Ab[(size_t)(bm + r0) * KA + kk0]);
    float4 va1 = *reinterpret_cast<const float4*>(&Ab[(size_t)(bm + r1) * KA + kk1]);
    float4 vb0 = *reinterpret_cast<const float4*>(&Bb[(size_t)(bn + r0) * KA + kk0]);
    float4 vb1 = *reinterpret_cast<const float4*>(&Bb[(size_t)(bn + r1) * KA + kk1]);

    for (int k0 = 0; k0 < KLEN; k0 += 16) {
        *reinterpret_cast<float4*>(&As[r0][kk0]) = va0;
        *reinterpret_cast<float4*>(&As[r1][kk1]) = va1;
        *reinterpret_cast<float4*>(&Bs[r0][kk0]) = vb0;
        *reinterpret_cast<float4*>(&Bs[r1][kk1]) = vb1;
        __syncthreads();

        if (k0 + 16 < KLEN) {
            va0 = *reinterpret_cast<const float4*>(&Ab[(size_t)(bm + r0) * KA + k0 + 16 + kk0]);
            va1 = *reinterpret_cast<const float4*>(&Ab[(size_t)(bm + r1) * KA + k0 + 16 + kk1]);
            vb0 = *reinterpret_cast<const float4*>(&Bb[(size_t)(bn + r0) * KA + k0 + 16 + kk0]);
            vb1 = *reinterpret_cast<const float4*>(&Bb[(size_t)(bn + r1) * KA + k0 + 16 + kk1]);
        }

        #pragma unroll
        for (int k8 = 0; k8 < 16; k8 += 8) {
            unsigned ahi[2][4], alo[2][4];
            #pragma unroll
            for (int i = 0; i < 2; i++) {
                int rb = wm + i * 16;
                float x0 = As[rb + qr][k8 + qc];
                float x1 = As[rb + 8 + qr][k8 + qc];
                float x2 = As[rb + qr][k8 + 4 + qc];
                float x3 = As[rb + 8 + qr][k8 + 4 + qc];
                tf32_split(x0, ahi[i][0], alo[i][0]);
                tf32_split(x1, ahi[i][1], alo[i][1]);
                tf32_split(x2, ahi[i][2], alo[i][2]);
                tf32_split(x3, ahi[i][3], alo[i][3]);
            }
            unsigned bhi[4][2], blo[4][2];
            #pragma unroll
            for (int j = 0; j < 4; j++) {
                int nb = wn + j * 8;
                float y0 = Bs[nb + qr][k8 + qc];
                float y1 = Bs[nb + qr][k8 + 4 + qc];
                tf32_split(y0, bhi[j][0], blo[j][0]);
                tf32_split(y1, bhi[j][1], blo[j][1]);
            }
            #pragma unroll
            for (int i = 0; i < 2; i++)
                #pragma unroll
                for (int j = 0; j < 4; j++) {
                    mma_tf32(acc[i][j], ahi[i], bhi[j]);
                    mma_tf32(acc[i][j], ahi[i], blo[j]);
                    mma_tf32(acc[i][j], alo[i], bhi[j]);
                }
        }
        __syncthreads();
    }

    #pragma unroll
    for (int i = 0; i < 2; i++)
        #pragma unroll
        for (int j = 0; j < 4; j++) {
            int row = bm + wm + i * 16 + qr;
            int col = bn + wn + j * 8 + qc * 2;
            atomicAdd(&C[(size_t)row * N + col],       acc[i][j][0]);
            atomicAdd(&C[(size_t)row * N + col + 1],   acc[i][j][1]);
            atomicAdd(&C[(size_t)(row + 8) * N + col],     acc[i][j][2]);
            atomicAdd(&C[(size_t)(row + 8) * N + col + 1], acc[i][j][3]);
        }
}

__global__ void k3_gemm_cc(const float* __restrict__ conv_w) {
    gemm_nt_tf32<BI * 3, DD, DD, 256>(g_cmat, conv_w, g_cc);
}
__global__ void k5_gemm_dot() {
    gemm_nt_tf32<BI * 3, BC, DD, 128>(g_cc, g_capv, g_dot);
}

// ---------------- K6: fused Gram + final similarity ----------------
// Block i: compute G[6], h[3] from cc rows (k4's job), then per-thread b similarity.
__global__ void k6_final(const float* __restrict__ conv_b, float* __restrict__ out) {
    int i = blockIdx.x;
    int tid = threadIdx.x;   // 256
    const float4* c0 = reinterpret_cast<const float4*>(g_cc + (size_t)(i * 3 + 0) * DD);
    const float4* c1 = reinterpret_cast<const float4*>(g_cc + (size_t)(i * 3 + 1) * DD);
    const float4* c2 = reinterpret_cast<const float4*>(g_cc + (size_t)(i * 3 + 2) * DD);
    const float4* cb = reinterpret_cast<const float4*>(conv_b);
    float4 x0 = c0[tid], x1 = c1[tid], x2 = c2[tid], b4 = cb[tid];
    float a[9];
    a[0] = x0.x*x0.x + x0.y*x0.y + x0.z*x0.z + x0.w*x0.w;
    a[1] = x0.x*x1.x + x0.y*x1.y + x0.z*x1.z + x0.w*x1.w;
    a[2] = x0.x*x2.x + x0.y*x2.y + x0.z*x2.z + x0.w*x2.w;
    a[3] = x1.x*x1.x + x1.y*x1.y + x1.z*x1.z + x1.w*x1.w;
    a[4] = x1.x*x2.x + x1.y*x2.y + x1.z*x2.z + x1.w*x2.w;
    a[5] = x2.x*x2.x + x2.y*x2.y + x2.z*x2.z + x2.w*x2.w;
    a[6] = x0.x*b4.x + x0.y*b4.y + x0.z*b4.z + x0.w*b4.w;
    a[7] = x1.x*b4.x + x1.y*b4.y + x1.z*b4.z + x1.w*b4.w;
    a[8] = x2.x*b4.x + x2.y*b4.y + x2.z*b4.z + x2.w*b4.w;

    __shared__ float sred[8][9];
    __shared__ float gh[9];
    int lane = tid & 31, wid = tid >> 5;
    #pragma unroll
    for (int r = 0; r < 9; r++) {
        float v = a[r];
        #pragma unroll
        for (int off = 16; off > 0; off >>= 1) v += __shfl_down_sync(0xffffffffu, v, off);
        if (lane == 0) sred[wid][r] = v;
    }
    __syncthreads();
    if (wid == 0) {
        #pragma unroll
        for (int r = 0; r < 9; r++) {
            float v = (lane < 8) ? sred[lane][r] : 0.f;
            #pragma unroll
            for (int off = 4; off > 0; off >>= 1) v += __shfl_down_sync(0xffffffffu, v, off);
            if (lane == 0) gh[r] = v;
        }
    }
    __syncthreads();

    int b = tid;
    float w0 = g_w[b * 3 + 0], w1 = g_w[b * 3 + 1], w2 = g_w[b * 3 + 2];
    const float* dp = g_dot + (size_t)(i * 3) * BC + b;
    float num = w0 * dp[0] + w1 * dp[BC] + w2 * dp[2 * BC] + g_bb[b];
    float n2 = w0 * w0 * gh[0] + 2.f * w0 * w1 * gh[1] + 2.f * w0 * w2 * gh[2]
             + w1 * w1 * gh[3] + 2.f * w1 * w2 * gh[4] + w2 * w2 * gh[5]
             + 2.f * (w0 * gh[6] + w1 * gh[7] + w2 * gh[8]) + g_cb2;
    out[i * BC + b] = num / (sqrtf(n2) + EPS);
}

// ---------------- launch (R11 fork-join schedule; k4 fused into k6) ----------------
extern "C" void kernel_launch(void* const* d_in, const int* in_sizes, int n_in,
                              void* d_out, int out_size) {
    const float* img    = (const float*)d_in[0];
    const float* cap    = (const float*)d_in[1];
    const int*   lens   = (const int*)d_in[2];
    const float* red_w  = (const float*)d_in[3];
    const float* red_b  = (const float*)d_in[4];
    const float* proj_w = (const float*)d_in[5];
    const float* proj_b = (const float*)d_in[6];
    const float* conv_w = (const float*)d_in[7];
    const float* conv_b = (const float*)d_in[8];
    float* out = (float*)d_out;

    float* zbuf = nullptr;
    cudaGetSymbolAddress((void**)&zbuf, g_zbuf);

    // Streams/events created per call; not destroyed (host handles only; see R7 note).
    cudaStream_t s2;
    cudaStreamCreateWithFlags(&s2, cudaStreamNonBlocking);
    cudaEvent_t e_zero, e_cap;
    cudaEventCreateWithFlags(&e_zero, cudaEventDisableTiming);
    cudaEventCreateWithFlags(&e_cap, cudaEventDisableTiming);

    // main stream: zero everything, then image chain
    kzero<<<(ZB_TOTAL / 4 + 255) / 256, 256>>>(zbuf, ZB_TOTAL / 4);
    cudaEventRecord(e_zero, 0);

    // forked stream: caption chain
    cudaStreamWaitEvent(s2, e_zero, 0);
    k0_prep<<<9, 128, 0, s2>>>(red_w, red_b, proj_w, proj_b, conv_b);
    k1a_capsum<<<dim3(BC, 4), 256, 0, s2>>>(cap, lens);
    k1b_caption<<<BC, 256, 0, s2>>>(lens, conv_b);
    cudaEventRecord(e_cap, s2);

    // main stream: image chain (overlaps with caption chain)
    k2_image<<<dim3(BI, 2), 256>>>(img);
    k3_gemm_cc<<<dim3(DD / 64, (BI * 3) / 64, 4), 128>>>(conv_w);

    // join, then final GEMM + fused gram/similarity
    cudaStreamWaitEvent(0, e_cap, 0);
    k5_gemm_dot<<<dim3(BC / 64, (BI * 3) / 64, 8), 128>>>();
    k6_final<<<BI, 256>>>(conv_b, out);
}